// round 1
// baseline (speedup 1.0000x reference)
#include <cuda_runtime.h>
#include <math.h>

#define GAMMA 0.99f
#define GT    (0.99f * 0.95f)

constexpr int THREADS = 256;
constexpr int ITEMS   = 16;
constexpr int CHUNK   = THREADS * ITEMS;   // 4096 elements per block
constexpr int NB_MAX  = 65536;
constexpr int TILE2   = 1024;

// Scratch (no allocation allowed — device globals)
__device__ float4 g_blk[NB_MAX];    // per-block affine summary: (a_vt, b_vt, a_A, b_A)
__device__ float2 g_carry[NB_MAX];  // per-block incoming carry values (vt, A)
__device__ double g_sum_d;
__device__ double g_ssq_d;

__device__ __forceinline__ float4 comp4(float4 lo, float4 hi) {
    // lo covers lower indices; carry flows high->low: f_lo(f_hi(c))
    float4 o;
    o.x = lo.x * hi.x;
    o.y = lo.y + lo.x * hi.y;
    o.z = lo.z * hi.z;
    o.w = lo.w + lo.z * hi.w;
    return o;
}

__global__ void k_init() { g_sum_d = 0.0; g_ssq_d = 0.0; }

struct ThreadData {
    float rr[ITEMS];
    float vv[ITEMS];
    float mm[ITEMS];
    float vlast;   // v[s+ITEMS] or 0
    int   nvalid;
};

__device__ __forceinline__ void load_chunk(const float* __restrict__ r,
                                           const float* __restrict__ v,
                                           const int*   __restrict__ m,
                                           long s, long B, ThreadData& td) {
    long rem = B - s;
    td.nvalid = (rem >= ITEMS) ? ITEMS : (rem > 0 ? (int)rem : 0);
    if (td.nvalid == ITEMS) {
#pragma unroll
        for (int j = 0; j < ITEMS / 4; j++) {
            float4 x = *reinterpret_cast<const float4*>(r + s + 4 * j);
            float4 y = *reinterpret_cast<const float4*>(v + s + 4 * j);
            int4  mi = *reinterpret_cast<const int4*>(m + s + 4 * j);
            td.rr[4*j+0] = x.x; td.rr[4*j+1] = x.y; td.rr[4*j+2] = x.z; td.rr[4*j+3] = x.w;
            td.vv[4*j+0] = y.x; td.vv[4*j+1] = y.y; td.vv[4*j+2] = y.z; td.vv[4*j+3] = y.w;
            td.mm[4*j+0] = (float)mi.x; td.mm[4*j+1] = (float)mi.y;
            td.mm[4*j+2] = (float)mi.z; td.mm[4*j+3] = (float)mi.w;
        }
    } else {
#pragma unroll
        for (int i = 0; i < ITEMS; i++) {
            if (i < td.nvalid) {
                td.rr[i] = r[s + i];
                td.vv[i] = v[s + i];
                td.mm[i] = (float)m[s + i];
            } else {
                td.rr[i] = 0.f; td.vv[i] = 0.f; td.mm[i] = 0.f;
            }
        }
    }
    td.vlast = (s + ITEMS < B) ? v[s + ITEMS] : 0.f;
}

// Serial reverse scan over the thread's chunk with zero carry -> affine summary
__device__ __forceinline__ float4 summarize(const ThreadData& td) {
    float av = 1.f, bv = 0.f, aa = 1.f, ba = 0.f;
#pragma unroll
    for (int i = ITEMS - 1; i >= 0; i--) {
        if (i < td.nvalid) {
            float mi = td.mm[i];
            float vnext = (i + 1 < ITEMS) ? td.vv[i + 1] : td.vlast;
            float a1 = GAMMA * mi;
            bv = td.rr[i] + a1 * bv;
            av *= a1;
            float delta = td.rr[i] + GAMMA * vnext * mi - td.vv[i];
            float a2 = GT * mi;
            ba = delta + a2 * ba;
            aa *= a2;
        }
    }
    return make_float4(av, bv, aa, ba);
}

// ---------------- Pass 1: per-block summaries ----------------
__global__ void k_pass1(const float* __restrict__ r, const float* __restrict__ v,
                        const int* __restrict__ m, long B) {
    __shared__ float4 S[THREADS];
    int t = threadIdx.x;
    long base = (long)blockIdx.x * CHUNK;
    ThreadData td;
    load_chunk(r, v, m, base + (long)t * ITEMS, B, td);
    S[t] = summarize(td);
    __syncthreads();
    // ordered tree reduction (non-commutative compose)
    for (int str = THREADS / 2; str > 0; str >>= 1) {
        if (t < str) S[t] = comp4(S[t], S[t + str]);
        __syncthreads();
    }
    if (t == 0) g_blk[blockIdx.x] = S[0];
}

// ---------------- Pass 2: scan block summaries -> per-block carry-in ----------------
__global__ void k_pass2(int NB) {
    __shared__ float4 S[TILE2];
    int j = threadIdx.x;
    float2 cr = make_float2(0.f, 0.f);  // carry value entering from the right
    int ntiles = (NB + TILE2 - 1) / TILE2;
    for (int tile = ntiles - 1; tile >= 0; tile--) {
        int b = tile * TILE2 + j;
        float4 f = (b < NB) ? g_blk[b] : make_float4(1.f, 0.f, 1.f, 0.f);
        S[j] = f;
        __syncthreads();
        // Hillis-Steele suffix composition: after, S[j] = f_j o ... o f_{TILE-1}
        for (int d = 1; d < TILE2; d <<= 1) {
            float4 cur = S[j];
            float4 hi = (j + d < TILE2) ? S[j + d] : make_float4(1.f, 0.f, 1.f, 0.f);
            __syncthreads();
            S[j] = comp4(cur, hi);
            __syncthreads();
        }
        float4 sn = (j + 1 < TILE2) ? S[j + 1] : make_float4(1.f, 0.f, 1.f, 0.f);
        float cv = sn.y + sn.x * cr.x;
        float ca = sn.w + sn.z * cr.y;
        if (b < NB) g_carry[b] = make_float2(cv, ca);
        float4 s0 = S[0];
        __syncthreads();  // everyone done reading S before next tile overwrites
        float2 ncr;
        ncr.x = s0.y + s0.x * cr.x;
        ncr.y = s0.w + s0.z * cr.y;
        cr = ncr;
    }
}

// ---------------- Pass 3: fixup + output + stats ----------------
__global__ void k_pass3(const float* __restrict__ r, const float* __restrict__ v,
                        const int* __restrict__ m,
                        float* __restrict__ outA, float* __restrict__ outVT, long B) {
    __shared__ float4 S[THREADS];
    __shared__ double DS[THREADS];
    __shared__ double DQ[THREADS];
    int t = threadIdx.x;
    long base = (long)blockIdx.x * CHUNK;
    long s = base + (long)t * ITEMS;
    ThreadData td;
    load_chunk(r, v, m, s, B, td);
    S[t] = summarize(td);
    __syncthreads();
    // suffix scan across threads
    for (int d = 1; d < THREADS; d <<= 1) {
        float4 cur = S[t];
        float4 hi = (t + d < THREADS) ? S[t + d] : make_float4(1.f, 0.f, 1.f, 0.f);
        __syncthreads();
        S[t] = comp4(cur, hi);
        __syncthreads();
    }
    float2 cb = g_carry[blockIdx.x];
    float cvt, ca;
    if (t == THREADS - 1) {
        cvt = cb.x; ca = cb.y;
    } else {
        float4 sn = S[t + 1];
        cvt = sn.y + sn.x * cb.x;
        ca  = sn.w + sn.z * cb.y;
    }
    // final serial pass: overwrite mm with v_target, rr with A
    double lsum = 0.0, lssq = 0.0;
#pragma unroll
    for (int i = ITEMS - 1; i >= 0; i--) {
        if (i < td.nvalid) {
            float mi = td.mm[i];
            float vnext = (i + 1 < ITEMS) ? td.vv[i + 1] : td.vlast;
            float vt = td.rr[i] + GAMMA * mi * cvt;
            float delta = td.rr[i] + GAMMA * vnext * mi - td.vv[i];
            float A = delta + GT * mi * ca;
            td.mm[i] = vt;
            td.rr[i] = A;
            cvt = vt;
            ca = A;
            lsum += (double)A;
            lssq += (double)A * (double)A;
        }
    }
    // stores
    bool vt_aligned = ((((unsigned long long)(outVT + s)) & 15ull) == 0);
    if (td.nvalid == ITEMS) {
#pragma unroll
        for (int j = 0; j < ITEMS / 4; j++) {
            *reinterpret_cast<float4*>(outA + s + 4 * j) =
                make_float4(td.rr[4*j+0], td.rr[4*j+1], td.rr[4*j+2], td.rr[4*j+3]);
        }
        if (vt_aligned) {
#pragma unroll
            for (int j = 0; j < ITEMS / 4; j++) {
                *reinterpret_cast<float4*>(outVT + s + 4 * j) =
                    make_float4(td.mm[4*j+0], td.mm[4*j+1], td.mm[4*j+2], td.mm[4*j+3]);
            }
        } else {
#pragma unroll
            for (int i = 0; i < ITEMS; i++) outVT[s + i] = td.mm[i];
        }
    } else {
        for (int i = 0; i < td.nvalid; i++) {
            outA[s + i] = td.rr[i];
            outVT[s + i] = td.mm[i];
        }
    }
    // block reduce stats
    DS[t] = lsum; DQ[t] = lssq;
    __syncthreads();
    for (int str = THREADS / 2; str > 0; str >>= 1) {
        if (t < str) { DS[t] += DS[t + str]; DQ[t] += DQ[t + str]; }
        __syncthreads();
    }
    if (t == 0) {
        atomicAdd(&g_sum_d, DS[0]);
        atomicAdd(&g_ssq_d, DQ[0]);
    }
}

// ---------------- Pass 4: normalize A ----------------
__global__ void k_norm(float* __restrict__ A, long B) {
    double sum = g_sum_d;
    double ssq = g_ssq_d;
    double mean = sum / (double)B;
    double var = (ssq - sum * mean) / (double)(B - 1);
    float fmean = (float)mean;
    float istd = (float)(1.0 / sqrt(var));
    long i = (long)blockIdx.x * blockDim.x + threadIdx.x;
    long stride = (long)gridDim.x * blockDim.x;
    for (; i < B; i += stride) {
        A[i] = (A[i] - fmean) * istd;
    }
}

extern "C" void kernel_launch(void* const* d_in, const int* in_sizes, int n_in,
                              void* d_out, int out_size) {
    const float* r = (const float*)d_in[0];
    const float* v = (const float*)d_in[1];
    const int*   m = (const int*)d_in[2];
    long B = (long)in_sizes[0];
    float* outA = (float*)d_out;
    float* outVT = outA + B;

    int NB = (int)((B + CHUNK - 1) / CHUNK);
    if (NB > NB_MAX) NB = NB_MAX;  // (B up to 256M supported; this problem: 1024 blocks)

    k_init<<<1, 1>>>();
    k_pass1<<<NB, THREADS>>>(r, v, m, B);
    k_pass2<<<1, TILE2>>>(NB);
    k_pass3<<<NB, THREADS>>>(r, v, m, outA, outVT, B);

    int nb4 = (int)((B + THREADS - 1) / THREADS);
    if (nb4 > 4096) nb4 = 4096;
    k_norm<<<nb4, THREADS>>>(outA, B);
}

// round 3
// speedup vs baseline: 2.5948x; 2.5948x over previous
#include <cuda_runtime.h>
#include <math.h>

#define GAMMA 0.99f
#define TAUF  0.95f

constexpr int THREADS = 256;
constexpr int ITEMS   = 8;
constexpr int CHUNK   = THREADS * ITEMS;   // 2048 elements per block
constexpr int NB_MAX  = 65536;
constexpr int NWARPS  = THREADS / 32;      // 8

// Scratch (device globals; no allocation allowed)
__device__ float4 g_blk[NB_MAX];    // per-block affine summary: (a_vt, b_vt, a_A, b_A)
__device__ float2 g_carry[NB_MAX];  // per-block incoming carry VALUES (vt, A)
__device__ float2 g_part[NB_MAX];   // per-block (sum, sumsq) of A
__device__ float2 g_normc;          // (mean, inv_std)

__device__ __forceinline__ float4 ident4() { return make_float4(1.f, 0.f, 1.f, 0.f); }

// lo covers lower (earlier) indices; carry flows high->low: result = f_lo(f_hi(c))
__device__ __forceinline__ float4 comp4(float4 lo, float4 hi) {
    float4 o;
    o.x = lo.x * hi.x;
    o.y = lo.y + lo.x * hi.y;
    o.z = lo.z * hi.z;
    o.w = lo.w + lo.z * hi.w;
    return o;
}

__device__ __forceinline__ float4 shfl_down4(float4 v, int d) {
    float4 o;
    o.x = __shfl_down_sync(0xffffffffu, v.x, d);
    o.y = __shfl_down_sync(0xffffffffu, v.y, d);
    o.z = __shfl_down_sync(0xffffffffu, v.z, d);
    o.w = __shfl_down_sync(0xffffffffu, v.w, d);
    return o;
}

// Inclusive SUFFIX scan within a warp: after, lane i holds f_i o f_{i+1} o ... o f_{31}
// ALL 32 lanes must execute this.
__device__ __forceinline__ float4 warp_suffix_scan(float4 v, int lane) {
#pragma unroll
    for (int d = 1; d < 32; d <<= 1) {
        float4 o = shfl_down4(v, d);
        if (lane + d < 32) v = comp4(v, o);
    }
    return v;
}

struct Tile {
    float rr[ITEMS];   // r
    float dd[ITEMS];   // delta
    float a1[ITEMS];   // gamma * mask
    int   nvalid;
};

__device__ __forceinline__ void load_tile(const float* __restrict__ r,
                                          const float* __restrict__ v,
                                          const int*   __restrict__ m,
                                          long s, long B, Tile& td) {
    float vv[ITEMS + 1];
    long rem = B - s;
    td.nvalid = (rem >= ITEMS) ? ITEMS : (rem > 0 ? (int)rem : 0);
    if (td.nvalid == ITEMS) {
#pragma unroll
        for (int j = 0; j < ITEMS / 4; j++) {
            float4 x = *reinterpret_cast<const float4*>(r + s + 4 * j);
            float4 y = *reinterpret_cast<const float4*>(v + s + 4 * j);
            int4  mi = *reinterpret_cast<const int4*>(m + s + 4 * j);
            td.rr[4*j+0] = x.x; td.rr[4*j+1] = x.y; td.rr[4*j+2] = x.z; td.rr[4*j+3] = x.w;
            vv[4*j+0] = y.x; vv[4*j+1] = y.y; vv[4*j+2] = y.z; vv[4*j+3] = y.w;
            td.a1[4*j+0] = GAMMA * (float)mi.x; td.a1[4*j+1] = GAMMA * (float)mi.y;
            td.a1[4*j+2] = GAMMA * (float)mi.z; td.a1[4*j+3] = GAMMA * (float)mi.w;
        }
        vv[ITEMS] = (s + ITEMS < B) ? v[s + ITEMS] : 0.f;
    } else {
#pragma unroll
        for (int i = 0; i < ITEMS; i++) {
            if (i < td.nvalid) {
                td.rr[i] = r[s + i];
                vv[i]    = v[s + i];
                td.a1[i] = GAMMA * (float)m[s + i];
            } else { td.rr[i] = 0.f; vv[i] = 0.f; td.a1[i] = 0.f; }
        }
        vv[ITEMS] = 0.f;
    }
#pragma unroll
    for (int i = 0; i < ITEMS; i++)
        td.dd[i] = td.rr[i] + td.a1[i] * vv[i + 1] - vv[i];
}

// Forward-order affine composition of the tile (F = f_0 o f_1 o ... )
__device__ __forceinline__ float4 tile_summary(const Tile& td) {
    float av = 1.f, bv = 0.f, aa = 1.f, ba = 0.f;
#pragma unroll
    for (int i = 0; i < ITEMS; i++) {
        if (i < td.nvalid) {
            float a1 = td.a1[i];
            float a2 = a1 * TAUF;
            bv = bv + av * td.rr[i]; av = av * a1;
            ba = ba + aa * td.dd[i]; aa = aa * a2;
        }
    }
    return make_float4(av, bv, aa, ba);
}

// ---------------- Pass 1: per-block summaries (pure streaming) ----------------
__global__ void __launch_bounds__(THREADS) k_pass1(const float* __restrict__ r,
                                                   const float* __restrict__ v,
                                                   const int* __restrict__ m, long B) {
    __shared__ float4 WAGG[NWARPS];
    int t = threadIdx.x, lane = t & 31, w = t >> 5;
    long s = (long)blockIdx.x * CHUNK + (long)t * ITEMS;
    Tile td;
    load_tile(r, v, m, s, B, td);
    float4 f = tile_summary(td);
    f = warp_suffix_scan(f, lane);          // lane0 now holds the warp aggregate
    if (lane == 0) WAGG[w] = f;
    __syncthreads();
    if (w == 0) {                           // WHOLE warp 0 participates in shuffles
        float4 a = (lane < NWARPS) ? WAGG[lane] : ident4();
#pragma unroll
        for (int d = 1; d < NWARPS; d <<= 1) {
            float4 o = shfl_down4(a, d);
            if (lane + d < NWARPS) a = comp4(a, o);
        }
        if (lane == 0) g_blk[blockIdx.x] = a;
    }
}

// ---------------- Pass 2: scan block summaries -> per-block carry values ----------------
// One block, 1024 threads, each handles a PAIR of consecutive block summaries.
__global__ void __launch_bounds__(1024) k_pass2(int NB) {
    __shared__ float4 WAGG[32];
    __shared__ float2 WCARRY[32];
    __shared__ float4 TILEAGG;
    int j = threadIdx.x, lane = j & 31, w = j >> 5;
    float2 cr = make_float2(0.f, 0.f);      // carry value entering this tile from the right
    int ntiles = (NB + 2047) / 2048;
    for (int tile = ntiles - 1; tile >= 0; tile--) {
        int b0 = tile * 2048 + 2 * j;
        float4 f0 = (b0     < NB) ? g_blk[b0]     : ident4();
        float4 f1 = (b0 + 1 < NB) ? g_blk[b0 + 1] : ident4();
        float4 e  = comp4(f0, f1);
        float4 sfx = warp_suffix_scan(e, lane);
        if (lane == 0) WAGG[w] = sfx;
        __syncthreads();
        if (w == 0) {                        // whole warp participates
            float4 sw = WAGG[lane];
#pragma unroll
            for (int d = 1; d < 32; d <<= 1) {
                float4 o = shfl_down4(sw, d);
                if (lane + d < 32) sw = comp4(sw, o);
            }
            float4 ex = shfl_down4(sw, 1);
            if (lane == 31) ex = ident4();
            float2 wc;
            wc.x = ex.y + ex.x * cr.x;
            wc.y = ex.w + ex.z * cr.y;
            WCARRY[lane] = wc;
            if (lane == 0) TILEAGG = sw;    // full tile composition
        }
        __syncthreads();
        float2 wcar = WCARRY[w];
        float4 X = shfl_down4(sfx, 1);
        if (lane == 31) X = ident4();
        float2 cpair;                        // carry entering element b0+1 from the right
        cpair.x = X.y + X.x * wcar.x;
        cpair.y = X.w + X.z * wcar.y;
        if (b0 + 1 < NB) g_carry[b0 + 1] = cpair;
        float2 c0;                           // carry entering element b0
        c0.x = f1.y + f1.x * cpair.x;
        c0.y = f1.w + f1.z * cpair.y;
        if (b0 < NB) g_carry[b0] = c0;
        float4 ta = TILEAGG;
        float2 ncr;
        ncr.x = ta.y + ta.x * cr.x;
        ncr.y = ta.w + ta.z * cr.y;
        cr = ncr;
        __syncthreads();                     // protect WAGG/TILEAGG before next tile
    }
}

// ---------------- Pass 3: fixup + outputs + per-block stats (no atomics) ----------------
__global__ void __launch_bounds__(THREADS) k_pass3(const float* __restrict__ r,
                                                   const float* __restrict__ v,
                                                   const int* __restrict__ m,
                                                   float* __restrict__ outA,
                                                   float* __restrict__ outVT, long B) {
    __shared__ float4 WAGG[NWARPS];
    __shared__ float2 WCARRY[NWARPS];
    __shared__ float2 WSUM[NWARPS];
    int t = threadIdx.x, lane = t & 31, w = t >> 5;
    long s = (long)blockIdx.x * CHUNK + (long)t * ITEMS;
    Tile td;
    load_tile(r, v, m, s, B, td);
    float4 f = tile_summary(td);
    float4 sfx = warp_suffix_scan(f, lane);
    if (lane == 0) WAGG[w] = sfx;
    __syncthreads();
    if (w == 0) {                           // whole warp 0 participates
        float4 sw = (lane < NWARPS) ? WAGG[lane] : ident4();
#pragma unroll
        for (int d = 1; d < NWARPS; d <<= 1) {
            float4 o = shfl_down4(sw, d);
            if (lane + d < NWARPS) sw = comp4(sw, o);
        }
        float4 ex = shfl_down4(sw, 1);
        if (lane >= NWARPS - 1) ex = ident4();
        float2 cb = g_carry[blockIdx.x];
        float2 wc;
        wc.x = ex.y + ex.x * cb.x;
        wc.y = ex.w + ex.z * cb.y;
        if (lane < NWARPS) WCARRY[lane] = wc;
    }
    __syncthreads();
    float2 wcar = WCARRY[w];
    float4 X = shfl_down4(sfx, 1);
    if (lane == 31) X = ident4();
    float cvt = X.y + X.x * wcar.x;   // carry values entering this thread's items
    float ca  = X.w + X.z * wcar.y;

    float sA = 0.f, sQ = 0.f;
#pragma unroll
    for (int i = ITEMS - 1; i >= 0; i--) {
        if (i < td.nvalid) {
            float a1 = td.a1[i];
            float vt = td.rr[i] + a1 * cvt;
            float A  = td.dd[i] + a1 * TAUF * ca;
            td.rr[i] = vt;
            td.dd[i] = A;
            cvt = vt; ca = A;
            sA += A; sQ += A * A;
        }
    }
    // stores
    if (td.nvalid == ITEMS) {
#pragma unroll
        for (int j2 = 0; j2 < ITEMS / 4; j2++) {
            *reinterpret_cast<float4*>(outA + s + 4 * j2) =
                make_float4(td.dd[4*j2+0], td.dd[4*j2+1], td.dd[4*j2+2], td.dd[4*j2+3]);
            *reinterpret_cast<float4*>(outVT + s + 4 * j2) =
                make_float4(td.rr[4*j2+0], td.rr[4*j2+1], td.rr[4*j2+2], td.rr[4*j2+3]);
        }
    } else {
        for (int i = 0; i < td.nvalid; i++) {
            outA[s + i]  = td.dd[i];
            outVT[s + i] = td.rr[i];
        }
    }
    // block stats reduction (float tree; cross-block combine in doubles later)
#pragma unroll
    for (int d = 16; d > 0; d >>= 1) {
        sA += __shfl_down_sync(0xffffffffu, sA, d);
        sQ += __shfl_down_sync(0xffffffffu, sQ, d);
    }
    if (lane == 0) WSUM[w] = make_float2(sA, sQ);
    __syncthreads();
    if (w == 0) {                           // whole warp 0 participates
        float2 p = (lane < NWARPS) ? WSUM[lane] : make_float2(0.f, 0.f);
        float a = p.x, q = p.y;
#pragma unroll
        for (int d = NWARPS / 2; d > 0; d >>= 1) {
            a += __shfl_down_sync(0xffffffffu, a, d);
            q += __shfl_down_sync(0xffffffffu, q, d);
        }
        if (lane == 0) g_part[blockIdx.x] = make_float2(a, q);
    }
}

// ---------------- Pass 4: reduce per-block stats -> mean, inv_std ----------------
__global__ void __launch_bounds__(1024) k_stats(int NB, long B) {
    __shared__ double DS[32], DQ[32];
    int t = threadIdx.x, lane = t & 31, w = t >> 5;
    double s = 0.0, q = 0.0;
    for (int i = t; i < NB; i += 1024) {
        float2 p = g_part[i];
        s += (double)p.x; q += (double)p.y;
    }
#pragma unroll
    for (int d = 16; d > 0; d >>= 1) {
        s += __shfl_down_sync(0xffffffffu, s, d);
        q += __shfl_down_sync(0xffffffffu, q, d);
    }
    if (lane == 0) { DS[w] = s; DQ[w] = q; }
    __syncthreads();
    if (w == 0) {                           // 32 warps wrote DS/DQ; whole warp reads
        s = DS[lane]; q = DQ[lane];
#pragma unroll
        for (int d = 16; d > 0; d >>= 1) {
            s += __shfl_down_sync(0xffffffffu, s, d);
            q += __shfl_down_sync(0xffffffffu, q, d);
        }
        if (lane == 0) {
            double mean = s / (double)B;
            double var  = (q - s * mean) / (double)(B - 1);
            g_normc = make_float2((float)mean, (float)(1.0 / sqrt(var)));
        }
    }
}

// ---------------- Pass 5: normalize A in place ----------------
__global__ void __launch_bounds__(THREADS) k_norm(float* __restrict__ A, long B) {
    float2 nc = g_normc;
    float mean = nc.x, istd = nc.y;
    long n4 = B >> 2;
    long i = (long)blockIdx.x * blockDim.x + threadIdx.x;
    long stride = (long)gridDim.x * blockDim.x;
    float4* A4 = reinterpret_cast<float4*>(A);
    for (; i < n4; i += stride) {
        float4 x = A4[i];
        x.x = (x.x - mean) * istd;
        x.y = (x.y - mean) * istd;
        x.z = (x.z - mean) * istd;
        x.w = (x.w - mean) * istd;
        A4[i] = x;
    }
    // tail (B not multiple of 4)
    long tail = n4 << 2;
    long j = tail + (long)blockIdx.x * blockDim.x + threadIdx.x;
    if (j < B) A[j] = (A[j] - mean) * istd;
}

extern "C" void kernel_launch(void* const* d_in, const int* in_sizes, int n_in,
                              void* d_out, int out_size) {
    const float* r = (const float*)d_in[0];
    const float* v = (const float*)d_in[1];
    const int*   m = (const int*)d_in[2];
    long B = (long)in_sizes[0];
    float* outA  = (float*)d_out;
    float* outVT = outA + B;

    int NB = (int)((B + CHUNK - 1) / CHUNK);
    if (NB > NB_MAX) NB = NB_MAX;   // this problem: B=4194304 -> NB=2048

    k_pass1<<<NB, THREADS>>>(r, v, m, B);
    k_pass2<<<1, 1024>>>(NB);
    k_pass3<<<NB, THREADS>>>(r, v, m, outA, outVT, B);
    k_stats<<<1, 1024>>>(NB, B);

    long n4 = (B + 3) / 4;
    int nbn = (int)((n4 + THREADS - 1) / THREADS);
    if (nbn > 4096) nbn = 4096;
    k_norm<<<nbn, THREADS>>>(outA, B);
}

// round 4
// speedup vs baseline: 3.0444x; 1.1732x over previous
#include <cuda_runtime.h>
#include <math.h>

#define GAMMA 0.99f
#define TAUF  0.95f

constexpr int THREADS = 256;
constexpr int ITEMS   = 8;
constexpr int CHUNK   = THREADS * ITEMS;   // 2048 elements per block
constexpr int NB_MAX  = 65536;
constexpr int NWARPS  = THREADS / 32;      // 8

// Scratch (device globals; no allocation allowed)
__device__ float4 g_blk[NB_MAX];     // per-block affine summary: (a_vt, b_vt, a_A, b_A)
__device__ float2 g_carry[NB_MAX];   // per-block incoming carry VALUES (vt, A)
__device__ float4 g_statA[NB_MAX];   // per-block (SP, SG, SPP, SPG)
__device__ float  g_statB[NB_MAX];   // per-block SGG
__device__ float2 g_normc;           // (mean, inv_std)

__device__ __forceinline__ float4 ident4() { return make_float4(1.f, 0.f, 1.f, 0.f); }

// lo covers lower (earlier) indices; carry flows high->low: result = f_lo(f_hi(c))
__device__ __forceinline__ float4 comp4(float4 lo, float4 hi) {
    float4 o;
    o.x = lo.x * hi.x;
    o.y = lo.y + lo.x * hi.y;
    o.z = lo.z * hi.z;
    o.w = lo.w + lo.z * hi.w;
    return o;
}

__device__ __forceinline__ float4 shfl_down4(float4 v, int d) {
    float4 o;
    o.x = __shfl_down_sync(0xffffffffu, v.x, d);
    o.y = __shfl_down_sync(0xffffffffu, v.y, d);
    o.z = __shfl_down_sync(0xffffffffu, v.z, d);
    o.w = __shfl_down_sync(0xffffffffu, v.w, d);
    return o;
}

// Inclusive SUFFIX scan within a warp; ALL 32 lanes must execute.
__device__ __forceinline__ float4 warp_suffix_scan(float4 v, int lane) {
#pragma unroll
    for (int d = 1; d < 32; d <<= 1) {
        float4 o = shfl_down4(v, d);
        if (lane + d < 32) v = comp4(v, o);
    }
    return v;
}

struct Tile {
    float rr[ITEMS];   // r
    float dd[ITEMS];   // delta
    float a1[ITEMS];   // gamma * mask
    int   nvalid;
};

__device__ __forceinline__ void load_tile(const float* __restrict__ r,
                                          const float* __restrict__ v,
                                          const int*   __restrict__ m,
                                          long s, long B, Tile& td) {
    float vv[ITEMS + 1];
    long rem = B - s;
    td.nvalid = (rem >= ITEMS) ? ITEMS : (rem > 0 ? (int)rem : 0);
    if (td.nvalid == ITEMS) {
#pragma unroll
        for (int j = 0; j < ITEMS / 4; j++) {
            float4 x = *reinterpret_cast<const float4*>(r + s + 4 * j);
            float4 y = *reinterpret_cast<const float4*>(v + s + 4 * j);
            int4  mi = *reinterpret_cast<const int4*>(m + s + 4 * j);
            td.rr[4*j+0] = x.x; td.rr[4*j+1] = x.y; td.rr[4*j+2] = x.z; td.rr[4*j+3] = x.w;
            vv[4*j+0] = y.x; vv[4*j+1] = y.y; vv[4*j+2] = y.z; vv[4*j+3] = y.w;
            td.a1[4*j+0] = GAMMA * (float)mi.x; td.a1[4*j+1] = GAMMA * (float)mi.y;
            td.a1[4*j+2] = GAMMA * (float)mi.z; td.a1[4*j+3] = GAMMA * (float)mi.w;
        }
        vv[ITEMS] = (s + ITEMS < B) ? v[s + ITEMS] : 0.f;
    } else {
#pragma unroll
        for (int i = 0; i < ITEMS; i++) {
            if (i < td.nvalid) {
                td.rr[i] = r[s + i];
                vv[i]    = v[s + i];
                td.a1[i] = GAMMA * (float)m[s + i];
            } else { td.rr[i] = 0.f; vv[i] = 0.f; td.a1[i] = 0.f; }
        }
        vv[ITEMS] = 0.f;
    }
#pragma unroll
    for (int i = 0; i < ITEMS; i++)
        td.dd[i] = td.rr[i] + td.a1[i] * vv[i + 1] - vv[i];
}

// Forward-order affine composition of the tile (F = f_0 o f_1 o ... )
__device__ __forceinline__ float4 tile_summary(const Tile& td) {
    float av = 1.f, bv = 0.f, aa = 1.f, ba = 0.f;
#pragma unroll
    for (int i = 0; i < ITEMS; i++) {
        if (i < td.nvalid) {
            float a1 = td.a1[i];
            float a2 = a1 * TAUF;
            bv = bv + av * td.rr[i]; av = av * a1;
            ba = ba + aa * td.dd[i]; aa = aa * a2;
        }
    }
    return make_float4(av, bv, aa, ba);
}

// ---------------- Pass 1: per-block summary + A-moment coefficients ----------------
// Emits: g_blk[b] (affine summary) and the 5 moment coefficients so that
//   sum_A(b)   = SP + SG * c
//   sum_A2(b)  = SPP + 2*SPG*c + SGG*c^2        (c = block's incoming A-carry)
__global__ void __launch_bounds__(THREADS) k_pass1(const float* __restrict__ r,
                                                   const float* __restrict__ v,
                                                   const int* __restrict__ m, long B) {
    __shared__ float4 WAGG[NWARPS];
    __shared__ float2 WC[NWARPS];               // (Pa, Ga) entering each warp (block-carry=0 basis)
    __shared__ float SS0[NWARPS], SS1[NWARPS], SS2[NWARPS], SS3[NWARPS], SS4[NWARPS];
    int t = threadIdx.x, lane = t & 31, w = t >> 5;
    long s = (long)blockIdx.x * CHUNK + (long)t * ITEMS;
    Tile td;
    load_tile(r, v, m, s, B, td);
    float4 f = tile_summary(td);
    float4 sfx = warp_suffix_scan(f, lane);
    if (lane == 0) WAGG[w] = sfx;
    __syncthreads();
    if (w == 0) {                               // whole warp 0
        float4 sw = (lane < NWARPS) ? WAGG[lane] : ident4();
#pragma unroll
        for (int d = 1; d < NWARPS; d <<= 1) {
            float4 o = shfl_down4(sw, d);
            if (lane + d < NWARPS) sw = comp4(sw, o);
        }
        if (lane == 0) g_blk[blockIdx.x] = sw;
        float4 ex = shfl_down4(sw, 1);
        if (lane >= NWARPS - 1) ex = ident4();
        if (lane < NWARPS) WC[lane] = make_float2(ex.w, ex.z);   // (Pa, Ga) of warp
    }
    __syncthreads();
    float2 wc = WC[w];
    float4 X = shfl_down4(sfx, 1);
    if (lane == 31) X = ident4();
    // carry entering this thread's items as function of block carry c: P + G*c
    float P = X.w + X.z * wc.x;
    float G = X.z * wc.y;
    float sp = 0.f, sg = 0.f, spp = 0.f, spg = 0.f, sgg = 0.f;
#pragma unroll
    for (int i = ITEMS - 1; i >= 0; i--) {
        if (i < td.nvalid) {
            float a2 = td.a1[i] * TAUF;
            P = td.dd[i] + a2 * P;
            G = a2 * G;
            sp += P; sg += G;
            spp += P * P; spg += P * G; sgg += G * G;
        }
    }
    // block-wide reduction of the 5 stats
#pragma unroll
    for (int d = 16; d > 0; d >>= 1) {
        sp  += __shfl_down_sync(0xffffffffu, sp, d);
        sg  += __shfl_down_sync(0xffffffffu, sg, d);
        spp += __shfl_down_sync(0xffffffffu, spp, d);
        spg += __shfl_down_sync(0xffffffffu, spg, d);
        sgg += __shfl_down_sync(0xffffffffu, sgg, d);
    }
    if (lane == 0) { SS0[w] = sp; SS1[w] = sg; SS2[w] = spp; SS3[w] = spg; SS4[w] = sgg; }
    __syncthreads();
    if (w == 0) {                               // whole warp 0
        bool ok = lane < NWARPS;
        float a0 = ok ? SS0[lane] : 0.f;
        float a1 = ok ? SS1[lane] : 0.f;
        float a2 = ok ? SS2[lane] : 0.f;
        float a3 = ok ? SS3[lane] : 0.f;
        float a4 = ok ? SS4[lane] : 0.f;
#pragma unroll
        for (int d = NWARPS / 2; d > 0; d >>= 1) {
            a0 += __shfl_down_sync(0xffffffffu, a0, d);
            a1 += __shfl_down_sync(0xffffffffu, a1, d);
            a2 += __shfl_down_sync(0xffffffffu, a2, d);
            a3 += __shfl_down_sync(0xffffffffu, a3, d);
            a4 += __shfl_down_sync(0xffffffffu, a4, d);
        }
        if (lane == 0) {
            g_statA[blockIdx.x] = make_float4(a0, a1, a2, a3);
            g_statB[blockIdx.x] = a4;
        }
    }
}

// ---------------- Pass 2: block-summary scan -> carries, + global stats -> normc ----------------
__global__ void __launch_bounds__(1024) k_pass2(int NB, long B) {
    __shared__ float4 WAGG[32];
    __shared__ float2 WCARRY[32];
    __shared__ float4 TILEAGG;
    __shared__ double DS[32], DQ[32];
    int j = threadIdx.x, lane = j & 31, w = j >> 5;
    float2 cr = make_float2(0.f, 0.f);
    double dsum = 0.0, dssq = 0.0;
    int ntiles = (NB + 2047) / 2048;
    for (int tile = ntiles - 1; tile >= 0; tile--) {
        int b0 = tile * 2048 + 2 * j;
        float4 f0 = (b0     < NB) ? g_blk[b0]     : ident4();
        float4 f1 = (b0 + 1 < NB) ? g_blk[b0 + 1] : ident4();
        float4 e  = comp4(f0, f1);
        float4 sfx = warp_suffix_scan(e, lane);
        if (lane == 0) WAGG[w] = sfx;
        __syncthreads();
        if (w == 0) {
            float4 sw = WAGG[lane];
#pragma unroll
            for (int d = 1; d < 32; d <<= 1) {
                float4 o = shfl_down4(sw, d);
                if (lane + d < 32) sw = comp4(sw, o);
            }
            float4 ex = shfl_down4(sw, 1);
            if (lane == 31) ex = ident4();
            float2 wcv;
            wcv.x = ex.y + ex.x * cr.x;
            wcv.y = ex.w + ex.z * cr.y;
            WCARRY[lane] = wcv;
            if (lane == 0) TILEAGG = sw;
        }
        __syncthreads();
        float2 wcar = WCARRY[w];
        float4 X = shfl_down4(sfx, 1);
        if (lane == 31) X = ident4();
        float2 cpair;                        // carry entering block b0+1
        cpair.x = X.y + X.x * wcar.x;
        cpair.y = X.w + X.z * wcar.y;
        float2 c0;                           // carry entering block b0
        c0.x = f1.y + f1.x * cpair.x;
        c0.y = f1.w + f1.z * cpair.y;
        if (b0 + 1 < NB) {
            g_carry[b0 + 1] = cpair;
            float4 sA = g_statA[b0 + 1]; float sB = g_statB[b0 + 1];
            float c = cpair.y;
            dsum += (double)(sA.x + sA.y * c);
            dssq += (double)(sA.z + 2.f * sA.w * c + sB * c * c);
        }
        if (b0 < NB) {
            g_carry[b0] = c0;
            float4 sA = g_statA[b0]; float sB = g_statB[b0];
            float c = c0.y;
            dsum += (double)(sA.x + sA.y * c);
            dssq += (double)(sA.z + 2.f * sA.w * c + sB * c * c);
        }
        float4 ta = TILEAGG;
        float2 ncr;
        ncr.x = ta.y + ta.x * cr.x;
        ncr.y = ta.w + ta.z * cr.y;
        cr = ncr;
        __syncthreads();
    }
    // reduce global stats (doubles)
#pragma unroll
    for (int d = 16; d > 0; d >>= 1) {
        dsum += __shfl_down_sync(0xffffffffu, dsum, d);
        dssq += __shfl_down_sync(0xffffffffu, dssq, d);
    }
    if (lane == 0) { DS[w] = dsum; DQ[w] = dssq; }
    __syncthreads();
    if (w == 0) {
        double s = DS[lane], q = DQ[lane];
#pragma unroll
        for (int d = 16; d > 0; d >>= 1) {
            s += __shfl_down_sync(0xffffffffu, s, d);
            q += __shfl_down_sync(0xffffffffu, q, d);
        }
        if (lane == 0) {
            double mean = s / (double)B;
            double var  = (q - s * mean) / (double)(B - 1);
            g_normc = make_float2((float)mean, (float)(1.0 / sqrt(var)));
        }
    }
}

// ---------------- Pass 3: fixup + write v_target and NORMALIZED A ----------------
__global__ void __launch_bounds__(THREADS) k_pass3(const float* __restrict__ r,
                                                   const float* __restrict__ v,
                                                   const int* __restrict__ m,
                                                   float* __restrict__ outA,
                                                   float* __restrict__ outVT, long B) {
    __shared__ float4 WAGG[NWARPS];
    __shared__ float2 WCARRY[NWARPS];
    int t = threadIdx.x, lane = t & 31, w = t >> 5;
    long s = (long)blockIdx.x * CHUNK + (long)t * ITEMS;
    Tile td;
    load_tile(r, v, m, s, B, td);
    float2 nc = g_normc;
    float4 f = tile_summary(td);
    float4 sfx = warp_suffix_scan(f, lane);
    if (lane == 0) WAGG[w] = sfx;
    __syncthreads();
    if (w == 0) {
        float4 sw = (lane < NWARPS) ? WAGG[lane] : ident4();
#pragma unroll
        for (int d = 1; d < NWARPS; d <<= 1) {
            float4 o = shfl_down4(sw, d);
            if (lane + d < NWARPS) sw = comp4(sw, o);
        }
        float4 ex = shfl_down4(sw, 1);
        if (lane >= NWARPS - 1) ex = ident4();
        float2 cb = g_carry[blockIdx.x];
        float2 wc;
        wc.x = ex.y + ex.x * cb.x;
        wc.y = ex.w + ex.z * cb.y;
        if (lane < NWARPS) WCARRY[lane] = wc;
    }
    __syncthreads();
    float2 wcar = WCARRY[w];
    float4 X = shfl_down4(sfx, 1);
    if (lane == 31) X = ident4();
    float cvt = X.y + X.x * wcar.x;
    float ca  = X.w + X.z * wcar.y;

    float mean = nc.x, istd = nc.y;
#pragma unroll
    for (int i = ITEMS - 1; i >= 0; i--) {
        if (i < td.nvalid) {
            float a1 = td.a1[i];
            float vt = td.rr[i] + a1 * cvt;
            float A  = td.dd[i] + a1 * TAUF * ca;
            td.rr[i] = vt;
            cvt = vt; ca = A;
            td.dd[i] = (A - mean) * istd;   // normalized in place
        }
    }
    if (td.nvalid == ITEMS) {
#pragma unroll
        for (int j2 = 0; j2 < ITEMS / 4; j2++) {
            *reinterpret_cast<float4*>(outA + s + 4 * j2) =
                make_float4(td.dd[4*j2+0], td.dd[4*j2+1], td.dd[4*j2+2], td.dd[4*j2+3]);
            *reinterpret_cast<float4*>(outVT + s + 4 * j2) =
                make_float4(td.rr[4*j2+0], td.rr[4*j2+1], td.rr[4*j2+2], td.rr[4*j2+3]);
        }
    } else {
        for (int i = 0; i < td.nvalid; i++) {
            outA[s + i]  = td.dd[i];
            outVT[s + i] = td.rr[i];
        }
    }
}

extern "C" void kernel_launch(void* const* d_in, const int* in_sizes, int n_in,
                              void* d_out, int out_size) {
    const float* r = (const float*)d_in[0];
    const float* v = (const float*)d_in[1];
    const int*   m = (const int*)d_in[2];
    long B = (long)in_sizes[0];
    float* outA  = (float*)d_out;
    float* outVT = outA + B;

    int NB = (int)((B + CHUNK - 1) / CHUNK);
    if (NB > NB_MAX) NB = NB_MAX;   // this problem: B=4194304 -> NB=2048

    k_pass1<<<NB, THREADS>>>(r, v, m, B);
    k_pass2<<<1, 1024>>>(NB, B);
    k_pass3<<<NB, THREADS>>>(r, v, m, outA, outVT, B);
}